// round 3
// baseline (speedup 1.0000x reference)
#include <cuda_runtime.h>
#include <cuda_bf16.h>
#include <math.h>
#include <mma.h>

using namespace nvcuda;

// Problem constants (fixed by setup_inputs)
#define BATCH 2
#define SEQ 128
#define MODEL_DIM 256
#define NUM_HEAD 8
#define HEAD_DIM 32
#define ROWS (BATCH * SEQ * SEQ)        // 32768 token rows
#define QKV_DIM (3 * MODEL_DIM)         // 768
#define LN_EPS 1e-5f
#define MASK_BIAS -1000000000.0f
#define SCALE 0.17677669529663687f      // 32^-0.5

// Scratch (device globals; no allocations allowed)
__device__ float g_xnorm[ROWS * MODEL_DIM];
__device__ float g_qkv[ROWS * QKV_DIM];
__device__ float g_att[ROWS * MODEL_DIM];
__device__ int   g_mask_kind;           // 0=u8 bytes, 1=int32, 2=float32

// ---------------------------------------------------------------------------
// Mask dtype probe (deterministic)
// ---------------------------------------------------------------------------
__global__ void detect_mask_kernel(const unsigned char* __restrict__ p) {
    if (threadIdx.x == 0 && blockIdx.x == 0) {
        int nzoff = 0, maxb = 0;
        for (int i = 0; i < 4096; i++) {
            int v = p[i];
            if (v > maxb) maxb = v;
            if ((i & 3) != 0 && v != 0) nzoff = 1;
        }
        g_mask_kind = nzoff ? (maxb > 1 ? 2 : 0) : 1;
    }
}

// ---------------------------------------------------------------------------
// LayerNorm: one warp per 256-wide row
// ---------------------------------------------------------------------------
__global__ __launch_bounds__(256) void ln_kernel(
    const float* __restrict__ x, const float* __restrict__ gamma,
    const float* __restrict__ beta, float* __restrict__ out) {
    int row = blockIdx.x * 8 + threadIdx.y;
    int lane = threadIdx.x;
    const float* xr = x + (size_t)row * MODEL_DIM;
    float v[8];
    float s = 0.f, s2 = 0.f;
#pragma unroll
    for (int i = 0; i < 8; i++) {
        v[i] = xr[lane + i * 32];
        s += v[i];
        s2 += v[i] * v[i];
    }
#pragma unroll
    for (int o = 16; o; o >>= 1) {
        s += __shfl_xor_sync(0xffffffffu, s, o);
        s2 += __shfl_xor_sync(0xffffffffu, s2, o);
    }
    float mean = s * (1.f / 256.f);
    float var = s2 * (1.f / 256.f) - mean * mean;
    float inv = rsqrtf(var + LN_EPS);
    float* orow = out + (size_t)row * MODEL_DIM;
#pragma unroll
    for (int i = 0; i < 8; i++) {
        int c = lane + i * 32;
        orow[c] = (v[i] - mean) * inv * gamma[c] + beta[c];
    }
}

// ---------------------------------------------------------------------------
// 3xTF32 tensor-core GEMM: C[M,N] = A[M,K] * W[N,K]^T, fp32-grade accuracy.
// 128x128 CTA tile, BK=32, 8 warps each owning a 32x64 warp tile
// (2x4 wmma 16x16x8 fragments). Register-prefetch double buffering.
// ---------------------------------------------------------------------------
#define LDAS 40   // padded smem leading dim (multiple of 8, 32B-aligned rows)

__global__ __launch_bounds__(256) void gemm_tf32_3x(
    const float* __restrict__ A, const float* __restrict__ W,
    float* __restrict__ C, int M, int N, int K) {
    __shared__ float As[128][LDAS];   // [m][k]
    __shared__ float Bs[128][LDAS];   // [n][k]
    int t = threadIdx.x;
    int m0 = blockIdx.y * 128;
    int n0 = blockIdx.x * 128;
    int warp = t >> 5;
    int wm = warp >> 1;               // 0..3 -> 32-row slab
    int wn = warp & 1;                // 0..1 -> 64-col slab
    int lrow = t >> 3;                // 0..31
    int lc = (t & 7) * 4;             // float4 column within 32-wide k tile

    wmma::fragment<wmma::accumulator, 16, 16, 8, float> acc[2][4];
#pragma unroll
    for (int i = 0; i < 2; i++)
#pragma unroll
        for (int j = 0; j < 4; j++) wmma::fill_fragment(acc[i][j], 0.f);

    const float* Ab = A + (size_t)m0 * K;
    const float* Wb = W + (size_t)n0 * K;

    float4 pa[4], pb[4];
#pragma unroll
    for (int i = 0; i < 4; i++) {
        pa[i] = *(const float4*)(Ab + (size_t)(lrow + 32 * i) * K + lc);
        pb[i] = *(const float4*)(Wb + (size_t)(lrow + 32 * i) * K + lc);
    }

    for (int k0 = 0; k0 < K; k0 += 32) {
#pragma unroll
        for (int i = 0; i < 4; i++) {
            *(float4*)&As[lrow + 32 * i][lc] = pa[i];
            *(float4*)&Bs[lrow + 32 * i][lc] = pb[i];
        }
        __syncthreads();
        if (k0 + 32 < K) {
#pragma unroll
            for (int i = 0; i < 4; i++) {
                pa[i] = *(const float4*)(Ab + (size_t)(lrow + 32 * i) * K + k0 + 32 + lc);
                pb[i] = *(const float4*)(Wb + (size_t)(lrow + 32 * i) * K + k0 + 32 + lc);
            }
        }
#pragma unroll
        for (int kk = 0; kk < 32; kk += 8) {
            wmma::fragment<wmma::matrix_a, 16, 16, 8, wmma::precision::tf32,
                           wmma::row_major> ah[2], al[2];
            wmma::fragment<wmma::matrix_b, 16, 16, 8, wmma::precision::tf32,
                           wmma::col_major> bh[4], bl[4];
#pragma unroll
            for (int i = 0; i < 2; i++) {
                wmma::load_matrix_sync(ah[i], &As[wm * 32 + i * 16][kk], LDAS);
#pragma unroll
                for (int e = 0; e < ah[i].num_elements; e++) {
                    float v = ah[i].x[e];
                    float h = wmma::__float_to_tf32(v);
                    al[i].x[e] = wmma::__float_to_tf32(v - h);
                    ah[i].x[e] = h;
                }
            }
#pragma unroll
            for (int j = 0; j < 4; j++) {
                wmma::load_matrix_sync(bh[j], &Bs[wn * 64 + j * 16][kk], LDAS);
#pragma unroll
                for (int e = 0; e < bh[j].num_elements; e++) {
                    float v = bh[j].x[e];
                    float h = wmma::__float_to_tf32(v);
                    bl[j].x[e] = wmma::__float_to_tf32(v - h);
                    bh[j].x[e] = h;
                }
            }
#pragma unroll
            for (int i = 0; i < 2; i++)
#pragma unroll
                for (int j = 0; j < 4; j++) {
                    wmma::mma_sync(acc[i][j], ah[i], bh[j], acc[i][j]);
                    wmma::mma_sync(acc[i][j], ah[i], bl[j], acc[i][j]);
                    wmma::mma_sync(acc[i][j], al[i], bh[j], acc[i][j]);
                }
        }
        __syncthreads();
    }

#pragma unroll
    for (int i = 0; i < 2; i++)
#pragma unroll
        for (int j = 0; j < 4; j++) {
            float* cp = C + (size_t)(m0 + wm * 32 + i * 16) * N + n0 + wn * 64 + j * 16;
            wmma::store_matrix_sync(cp, acc[i][j], N, wmma::mem_row_major);
        }
}

// ---------------------------------------------------------------------------
// Axial rotary: channels [0,32) of q and k sections
// ---------------------------------------------------------------------------
__global__ __launch_bounds__(256) void rope_kernel(float* __restrict__ qkv) {
    int row = blockIdx.x * 8 + (threadIdx.x >> 5);
    int t = threadIdx.x & 31;
    int sec = t >> 4;          // 0 = q, 1 = k
    int p = t & 15;            // pair index within the 32 rot channels
    int x = (row >> 7) & 127;
    int y = row & 127;
    int pos = (p < 8) ? x : y;
    int j = p & 7;
    float tl = -1.f + 2.f * (float)pos * (1.f / 127.f);
    float invf = expf(-1.1512925464970229f * (float)j);
    float theta = tl * invf;
    float c, s;
    sincosf(theta, &s, &c);
    float* base = qkv + (size_t)row * QKV_DIM + sec * MODEL_DIM + 2 * p;
    float a = base[0];
    float b = base[1];
    base[0] = a * c - b * s;
    base[1] = b * c + a * s;
}

// ---------------------------------------------------------------------------
// Attention: one CTA per (b*x, head). 128 threads, thread t owns q-row y=t.
// ---------------------------------------------------------------------------
__global__ __launch_bounds__(128) void attn_kernel(
    const float* __restrict__ qkv, const void* __restrict__ pmask,
    float* __restrict__ out) {
    int h = blockIdx.x & 7;
    int bx = blockIdx.x >> 3;       // b*128 + x
    extern __shared__ float sm[];
    float* Ks = sm;                 // 128*32
    float* Vs = Ks + 128 * 32;      // 128*32
    float* S  = Vs + 128 * 32;      // 128*129 (scores; also q staging)
    float* Ms = S + 128 * 129;      // 128 mask flags
    int t = threadIdx.x;
    size_t rowbase = (size_t)bx * 128;
    const float* base = qkv + rowbase * QKV_DIM;

    for (int e = t; e < 128 * 32; e += 128) {
        int y = e >> 5, d = e & 31;
        Ks[e] = base[(size_t)y * QKV_DIM + MODEL_DIM + h * HEAD_DIM + d];
        Vs[e] = base[(size_t)y * QKV_DIM + 2 * MODEL_DIM + h * HEAD_DIM + d];
    }
    for (int e = t; e < 128 * 32; e += 128) {
        int y = e >> 5, d = e & 31;
        S[y * 33 + d] = base[(size_t)y * QKV_DIM + h * HEAD_DIM + d];
    }
    {
        int kind = g_mask_kind;
        size_t midx = (size_t)bx * 128 + t;
        bool mset;
        if (kind == 0)      mset = ((const unsigned char*)pmask)[midx] != 0;
        else if (kind == 1) mset = ((const int*)pmask)[midx] != 0;
        else                mset = ((const float*)pmask)[midx] != 0.f;
        Ms[t] = mset ? 1.f : 0.f;
    }
    __syncthreads();

    float q[32];
#pragma unroll
    for (int d = 0; d < 32; d++) q[d] = S[t * 33 + d];
    __syncthreads();

    float mx = -1e30f;
    for (int k = 0; k < 128; k++) {
        const float4* kr = (const float4*)&Ks[k * 32];
        float s = 0.f;
#pragma unroll
        for (int jj = 0; jj < 8; jj++) {
            float4 kv = kr[jj];
            s += q[4 * jj + 0] * kv.x + q[4 * jj + 1] * kv.y +
                 q[4 * jj + 2] * kv.z + q[4 * jj + 3] * kv.w;
        }
        s = (Ms[k] != 0.f) ? MASK_BIAS : s * SCALE;
        S[t * 129 + k] = s;
        mx = fmaxf(mx, s);
    }
    float l = 0.f;
    for (int k = 0; k < 128; k++) {
        float p = __expf(S[t * 129 + k] - mx);
        S[t * 129 + k] = p;
        l += p;
    }
    float inv = 1.f / l;

    float acc[32];
#pragma unroll
    for (int d = 0; d < 32; d++) acc[d] = 0.f;
    for (int k = 0; k < 128; k++) {
        float p = S[t * 129 + k];
        const float4* vr = (const float4*)&Vs[k * 32];
#pragma unroll
        for (int jj = 0; jj < 8; jj++) {
            float4 vv = vr[jj];
            acc[4 * jj + 0] += p * vv.x;
            acc[4 * jj + 1] += p * vv.y;
            acc[4 * jj + 2] += p * vv.z;
            acc[4 * jj + 3] += p * vv.w;
        }
    }
    float* orow = out + (rowbase + t) * MODEL_DIM + h * HEAD_DIM;
#pragma unroll
    for (int jj = 0; jj < 8; jj++) {
        float4 o = make_float4(acc[4 * jj + 0] * inv, acc[4 * jj + 1] * inv,
                               acc[4 * jj + 2] * inv, acc[4 * jj + 3] * inv);
        *(float4*)(orow + 4 * jj) = o;
    }
}

// ---------------------------------------------------------------------------
extern "C" void kernel_launch(void* const* d_in, const int* in_sizes, int n_in,
                              void* d_out, int out_size) {
    const float* pair_act = (const float*)d_in[0];
    const void*  pair_mask = d_in[1];
    const float* ln_gamma = (const float*)d_in[2];
    const float* ln_beta  = (const float*)d_in[3];
    const float* Wqkv = (const float*)d_in[4];
    const float* Wout = (const float*)d_in[5];
    float* out = (float*)d_out;

    float* xnorm; cudaGetSymbolAddress((void**)&xnorm, g_xnorm);
    float* qkv;   cudaGetSymbolAddress((void**)&qkv, g_qkv);
    float* att;   cudaGetSymbolAddress((void**)&att, g_att);

    detect_mask_kernel<<<1, 32>>>((const unsigned char*)pair_mask);

    ln_kernel<<<ROWS / 8, dim3(32, 8)>>>(pair_act, ln_gamma, ln_beta, xnorm);

    gemm_tf32_3x<<<dim3(QKV_DIM / 128, ROWS / 128), 256>>>(
        xnorm, Wqkv, qkv, ROWS, QKV_DIM, MODEL_DIM);

    rope_kernel<<<ROWS / 8, 256>>>(qkv);

    int attn_smem = (128 * 32 * 2 + 128 * 129 + 128) * (int)sizeof(float);
    cudaFuncSetAttribute(attn_kernel,
                         cudaFuncAttributeMaxDynamicSharedMemorySize, attn_smem);
    attn_kernel<<<BATCH * SEQ * NUM_HEAD, 128, attn_smem>>>(qkv, pair_mask, att);

    gemm_tf32_3x<<<dim3(MODEL_DIM / 128, ROWS / 128), 256>>>(
        att, Wout, out, ROWS, MODEL_DIM, MODEL_DIM);
}

// round 7
// speedup vs baseline: 1.4661x; 1.4661x over previous
#include <cuda_runtime.h>
#include <cuda_bf16.h>
#include <math.h>
#include <cstdint>

// Problem constants (fixed by setup_inputs)
#define BATCH 2
#define SEQ 128
#define MODEL_DIM 256
#define NUM_HEAD 8
#define HEAD_DIM 32
#define ROWS (BATCH * SEQ * SEQ)        // 32768 token rows
#define QKV_DIM (3 * MODEL_DIM)         // 768
#define GK 256                          // GEMM K (= MODEL_DIM)
#define LN_EPS 1e-5f
#define MASK_BIAS -1000000000.0f
#define SCALE 0.17677669529663687f      // 32^-0.5

// Scratch (device globals; no allocations allowed)
__device__ __nv_bfloat16 g_xh[ROWS * MODEL_DIM];
__device__ __nv_bfloat16 g_xl[ROWS * MODEL_DIM];
__device__ float         g_qkv[ROWS * QKV_DIM];
__device__ __nv_bfloat16 g_ath[ROWS * MODEL_DIM];
__device__ __nv_bfloat16 g_atl[ROWS * MODEL_DIM];
__device__ __nv_bfloat16 g_wqh[QKV_DIM * MODEL_DIM];
__device__ __nv_bfloat16 g_wql[QKV_DIM * MODEL_DIM];
__device__ __nv_bfloat16 g_woh[MODEL_DIM * MODEL_DIM];
__device__ __nv_bfloat16 g_wol[MODEL_DIM * MODEL_DIM];
__device__ int g_mask_kind;             // 0=u8 bytes, 1=int32, 2=float32

// ---------------------------------------------------------------------------
__device__ __forceinline__ uint32_t smem_u32(const void* p) {
    uint32_t a;
    asm("{ .reg .u64 t; cvta.to.shared.u64 t, %1; cvt.u32.u64 %0, t; }"
        : "=r"(a) : "l"(p));
    return a;
}

#define CP_ASYNC16(dst, src) \
    asm volatile("cp.async.cg.shared.global [%0], [%1], 16;" \
        :: "r"(dst), "l"(src) : "memory")
#define CP_COMMIT() asm volatile("cp.async.commit_group;" ::: "memory")

#define LDSM4(r, addr) \
    asm volatile("ldmatrix.sync.aligned.m8n8.x4.shared.b16 {%0,%1,%2,%3}, [%4];" \
        : "=r"((r)[0]), "=r"((r)[1]), "=r"((r)[2]), "=r"((r)[3]) : "r"(addr))

#define MMA16816(c, a, b0, b1) \
    asm volatile("mma.sync.aligned.m16n8k16.row.col.f32.bf16.bf16.f32 " \
        "{%0,%1,%2,%3}, {%4,%5,%6,%7}, {%8,%9}, {%0,%1,%2,%3};" \
        : "+f"((c)[0]), "+f"((c)[1]), "+f"((c)[2]), "+f"((c)[3]) \
        : "r"((a)[0]), "r"((a)[1]), "r"((a)[2]), "r"((a)[3]), "r"(b0), "r"(b1))

// ===========================================================================
// Mask dtype probe (deterministic)
// ===========================================================================
__global__ void detect_mask_kernel(const unsigned char* __restrict__ p) {
    if (threadIdx.x == 0 && blockIdx.x == 0) {
        int nzoff = 0, maxb = 0;
        for (int i = 0; i < 4096; i++) {
            int v = p[i];
            if (v > maxb) maxb = v;
            if ((i & 3) != 0 && v != 0) nzoff = 1;
        }
        g_mask_kind = nzoff ? (maxb > 1 ? 2 : 0) : 1;
    }
}

// ===========================================================================
// LayerNorm fused with bf16 hi/lo split output
// ===========================================================================
__global__ __launch_bounds__(256) void ln_split_kernel(
    const float* __restrict__ x, const float* __restrict__ gamma,
    const float* __restrict__ beta,
    __nv_bfloat16* __restrict__ xh, __nv_bfloat16* __restrict__ xl) {
    int row = blockIdx.x * 8 + threadIdx.y;
    int lane = threadIdx.x;
    const float* xr = x + (size_t)row * MODEL_DIM;
    float v[8];
    float s = 0.f, s2 = 0.f;
#pragma unroll
    for (int i = 0; i < 8; i++) {
        v[i] = xr[lane + i * 32];
        s += v[i];
        s2 += v[i] * v[i];
    }
#pragma unroll
    for (int o = 16; o; o >>= 1) {
        s += __shfl_xor_sync(0xffffffffu, s, o);
        s2 += __shfl_xor_sync(0xffffffffu, s2, o);
    }
    float mean = s * (1.f / 256.f);
    float var = s2 * (1.f / 256.f) - mean * mean;
    float inv = rsqrtf(var + LN_EPS);
    size_t ob = (size_t)row * MODEL_DIM;
#pragma unroll
    for (int i = 0; i < 8; i++) {
        int c = lane + i * 32;
        float y = (v[i] - mean) * inv * gamma[c] + beta[c];
        __nv_bfloat16 h = __float2bfloat16_rn(y);
        xh[ob + c] = h;
        xl[ob + c] = __float2bfloat16_rn(y - __bfloat162float(h));
    }
}

// ===========================================================================
// Weight hi/lo split
// ===========================================================================
__global__ __launch_bounds__(256) void wsplit_kernel(
    const float* __restrict__ src, __nv_bfloat16* __restrict__ h,
    __nv_bfloat16* __restrict__ l, int n) {
    int i = blockIdx.x * 256 + threadIdx.x;
    if (i < n) {
        float v = src[i];
        __nv_bfloat16 hh = __float2bfloat16_rn(v);
        h[i] = hh;
        l[i] = __float2bfloat16_rn(v - __bfloat162float(hh));
    }
}

// ===========================================================================
// bf16 3-term GEMM: C[M,Ntot] = (Ah+Al)[M,256] * (Bh+Bl)[Ntot,256]^T
// CTA tile 128x128, BK=32, cp.async double buffer, ldmatrix + mma.m16n8k16.
// smem stage layout (bytes): Ah(10240) Al(10240) Bh(10240) Bl(10240)
// row stride 40 bf16 (80B) -> conflict-free ldmatrix, 16B aligned.
// ===========================================================================
#define GST 40960
#define GSM_TOTAL (2 * GST)

__global__ __launch_bounds__(256) void gemm_bf16x3(
    const __nv_bfloat16* __restrict__ Ah, const __nv_bfloat16* __restrict__ Al,
    const __nv_bfloat16* __restrict__ Bh, const __nv_bfloat16* __restrict__ Bl,
    float* __restrict__ C, int Ntot) {
    extern __shared__ char smc[];
    uint32_t sb = smem_u32(smc);
    const int t = threadIdx.x;
    const int lane = t & 31;
    const int warp = t >> 5;
    const int wm = warp >> 1;      // 0..3 -> 32 rows
    const int wn = warp & 1;       // 0..1 -> 64 cols
    const int m0 = blockIdx.y * 128;
    const int n0 = blockIdx.x * 128;

    float acc[2][8][4];
#pragma unroll
    for (int i = 0; i < 2; i++)
#pragma unroll
        for (int j = 0; j < 8; j++)
#pragma unroll
            for (int e = 0; e < 4; e++) acc[i][j][e] = 0.f;

    auto issue_stage = [&](int kt, int s) {
        int k0 = kt * 32;
        uint32_t sbase = sb + s * GST;
#pragma unroll
        for (int qq = 0; qq < 2; qq++) {
            int q = t + qq * 256;
            int row = q >> 2;
            int c8 = (q & 3) * 8;
            uint32_t doff = row * 80 + (q & 3) * 16;
            const __nv_bfloat16* ga  = Ah + (size_t)(m0 + row) * GK + k0 + c8;
            const __nv_bfloat16* gal = Al + (size_t)(m0 + row) * GK + k0 + c8;
            const __nv_bfloat16* gb  = Bh + (size_t)(n0 + row) * GK + k0 + c8;
            const __nv_bfloat16* gbl = Bl + (size_t)(n0 + row) * GK + k0 + c8;
            CP_ASYNC16(sbase + doff, ga);
            CP_ASYNC16(sbase + 10240 + doff, gal);
            CP_ASYNC16(sbase + 20480 + doff, gb);
            CP_ASYNC16(sbase + 30720 + doff, gbl);
        }
        CP_COMMIT();
    };

    issue_stage(0, 0);
#pragma unroll 1
    for (int kt = 0; kt < 8; kt++) {
        if (kt < 7) {
            issue_stage(kt + 1, (kt + 1) & 1);
            asm volatile("cp.async.wait_group 1;" ::: "memory");
        } else {
            asm volatile("cp.async.wait_group 0;" ::: "memory");
        }
        __syncthreads();

        uint32_t sbase = sb + (kt & 1) * GST;
        uint32_t sAh = sbase, sAl = sbase + 10240;
        uint32_t sBh = sbase + 20480, sBl = sbase + 30720;
#pragma unroll
        for (int ks = 0; ks < 2; ks++) {
            uint32_t ah[2][4], alr[2][4];
#pragma unroll
            for (int mi = 0; mi < 2; mi++) {
                uint32_t off = ((wm * 32 + mi * 16 + (lane & 15)) * 40 +
                                ks * 16 + (lane >> 4) * 8) * 2;
                LDSM4(ah[mi], sAh + off);
                LDSM4(alr[mi], sAl + off);
            }
            uint32_t bh[4][4], bl[4][4];
#pragma unroll
            for (int ng = 0; ng < 4; ng++) {
                uint32_t off = ((wn * 64 + ng * 16 + (lane & 15)) * 40 +
                                ks * 16 + (lane >> 4) * 8) * 2;
                LDSM4(bh[ng], sBh + off);
                LDSM4(bl[ng], sBl + off);
            }
#pragma unroll
            for (int mi = 0; mi < 2; mi++)
#pragma unroll
                for (int ng = 0; ng < 4; ng++)
#pragma unroll
                    for (int hf = 0; hf < 2; hf++) {
                        int ni = ng * 2 + hf;
                        MMA16816(acc[mi][ni], ah[mi], bh[ng][hf], bh[ng][hf + 2]);
                        MMA16816(acc[mi][ni], alr[mi], bh[ng][hf], bh[ng][hf + 2]);
                        MMA16816(acc[mi][ni], ah[mi], bl[ng][hf], bl[ng][hf + 2]);
                    }
        }
        __syncthreads();
    }

    // epilogue
#pragma unroll
    for (int mi = 0; mi < 2; mi++) {
        int mr = m0 + wm * 32 + mi * 16 + (lane >> 2);
#pragma unroll
        for (int ni = 0; ni < 8; ni++) {
            float* p0 = C + (size_t)mr * Ntot + n0 + wn * 64 + ni * 8 + (lane & 3) * 2;
            *(float2*)p0 = make_float2(acc[mi][ni][0], acc[mi][ni][1]);
            float* p1 = p0 + 8 * (size_t)Ntot;
            *(float2*)p1 = make_float2(acc[mi][ni][2], acc[mi][ni][3]);
        }
    }
}

// ===========================================================================
// Axial rotary: channels [0,32) of q and k sections
// ===========================================================================
__global__ __launch_bounds__(256) void rope_kernel(float* __restrict__ qkv) {
    int row = blockIdx.x * 8 + (threadIdx.x >> 5);
    int t = threadIdx.x & 31;
    int sec = t >> 4;          // 0 = q, 1 = k
    int p = t & 15;
    int x = (row >> 7) & 127;
    int y = row & 127;
    int pos = (p < 8) ? x : y;
    int j = p & 7;
    float tl = -1.f + 2.f * (float)pos * (1.f / 127.f);
    float invf = expf(-1.1512925464970229f * (float)j);
    float theta = tl * invf;
    float c, s;
    sincosf(theta, &s, &c);
    float* base = qkv + (size_t)row * QKV_DIM + sec * MODEL_DIM + 2 * p;
    float a = base[0];
    float b = base[1];
    base[0] = a * c - b * s;
    base[1] = b * c + a * s;
}

// ===========================================================================
// Attention: one CTA per (b*x, head); epilogue writes bf16 hi/lo for out-proj
// ===========================================================================
__global__ __launch_bounds__(128) void attn_kernel(
    const float* __restrict__ qkv, const void* __restrict__ pmask,
    __nv_bfloat16* __restrict__ oh, __nv_bfloat16* __restrict__ ol) {
    int h = blockIdx.x & 7;
    int bx = blockIdx.x >> 3;
    extern __shared__ float sm[];
    float* Ks = sm;                 // 128*32
    float* Vs = Ks + 128 * 32;      // 128*32
    float* S  = Vs + 128 * 32;      // 128*129
    float* Ms = S + 128 * 129;      // 128 mask flags
    int t = threadIdx.x;
    size_t rowbase = (size_t)bx * 128;
    const float* base = qkv + rowbase * QKV_DIM;

    for (int e = t; e < 128 * 32; e += 128) {
        int y = e >> 5, d = e & 31;
        Ks[e] = base[(size_t)y * QKV_DIM + MODEL_DIM + h * HEAD_DIM + d];
        Vs[e] = base[(size_t)y * QKV_DIM + 2 * MODEL_DIM + h * HEAD_DIM + d];
    }
    for (int e = t; e < 128 * 32; e += 128) {
        int y = e >> 5, d = e & 31;
        S[y * 33 + d] = base[(size_t)y * QKV_DIM + h * HEAD_DIM + d];
    }
    {
        int kind = g_mask_kind;
        size_t midx = (size_t)bx * 128 + t;
        bool mset;
        if (kind == 0)      mset = ((const unsigned char*)pmask)[midx] != 0;
        else if (kind == 1) mset = ((const int*)pmask)[midx] != 0;
        else                mset = ((const float*)pmask)[midx] != 0.f;
        Ms[t] = mset ? 1.f : 0.f;
    }
    __syncthreads();

    float q[32];
#pragma unroll
    for (int d = 0; d < 32; d++) q[d] = S[t * 33 + d];
    __syncthreads();

    float mx = -1e30f;
    for (int k = 0; k < 128; k++) {
        const float4* kr = (const float4*)&Ks[k * 32];
        float s = 0.f;
#pragma unroll
        for (int jj = 0; jj < 8; jj++) {
            float4 kv = kr[jj];
            s += q[4 * jj + 0] * kv.x + q[4 * jj + 1] * kv.y +
                 q[4 * jj + 2] * kv.z + q[4 * jj + 3] * kv.w;
        }
        s = (Ms[k] != 0.f) ? MASK_BIAS : s * SCALE;
        S[t * 129 + k] = s;
        mx = fmaxf(mx, s);
    }
    float l = 0.f;
    for (int k = 0; k < 128; k++) {
        float p = __expf(S[t * 129 + k] - mx);
        S[t * 129 + k] = p;
        l += p;
    }
    float inv = 1.f / l;

    float acc[32];
#pragma unroll
    for (int d = 0; d < 32; d++) acc[d] = 0.f;
    for (int k = 0; k < 128; k++) {
        float p = S[t * 129 + k];
        const float4* vr = (const float4*)&Vs[k * 32];
#pragma unroll
        for (int jj = 0; jj < 8; jj++) {
            float4 vv = vr[jj];
            acc[4 * jj + 0] += p * vv.x;
            acc[4 * jj + 1] += p * vv.y;
            acc[4 * jj + 2] += p * vv.z;
            acc[4 * jj + 3] += p * vv.w;
        }
    }
    size_t obase = (rowbase + t) * MODEL_DIM + h * HEAD_DIM;
#pragma unroll
    for (int d = 0; d < 32; d++) {
        float v = acc[d] * inv;
        __nv_bfloat16 hh = __float2bfloat16_rn(v);
        oh[obase + d] = hh;
        ol[obase + d] = __float2bfloat16_rn(v - __bfloat162float(hh));
    }
}

// ===========================================================================
extern "C" void kernel_launch(void* const* d_in, const int* in_sizes, int n_in,
                              void* d_out, int out_size) {
    const float* pair_act = (const float*)d_in[0];
    const void*  pair_mask = d_in[1];
    const float* ln_gamma = (const float*)d_in[2];
    const float* ln_beta  = (const float*)d_in[3];
    const float* Wqkv = (const float*)d_in[4];
    const float* Wout = (const float*)d_in[5];
    float* out = (float*)d_out;

    __nv_bfloat16 *xh, *xl, *ath, *atl, *wqh, *wql, *woh, *wol;
    float* qkv;
    cudaGetSymbolAddress((void**)&xh, g_xh);
    cudaGetSymbolAddress((void**)&xl, g_xl);
    cudaGetSymbolAddress((void**)&qkv, g_qkv);
    cudaGetSymbolAddress((void**)&ath, g_ath);
    cudaGetSymbolAddress((void**)&atl, g_atl);
    cudaGetSymbolAddress((void**)&wqh, g_wqh);
    cudaGetSymbolAddress((void**)&wql, g_wql);
    cudaGetSymbolAddress((void**)&woh, g_woh);
    cudaGetSymbolAddress((void**)&wol, g_wol);

    detect_mask_kernel<<<1, 32>>>((const unsigned char*)pair_mask);

    ln_split_kernel<<<ROWS / 8, dim3(32, 8)>>>(pair_act, ln_gamma, ln_beta, xh, xl);
    wsplit_kernel<<<(QKV_DIM * MODEL_DIM + 255) / 256, 256>>>(
        Wqkv, wqh, wql, QKV_DIM * MODEL_DIM);
    wsplit_kernel<<<(MODEL_DIM * MODEL_DIM + 255) / 256, 256>>>(
        Wout, woh, wol, MODEL_DIM * MODEL_DIM);

    cudaFuncSetAttribute(gemm_bf16x3,
                         cudaFuncAttributeMaxDynamicSharedMemorySize, GSM_TOTAL);
    gemm_bf16x3<<<dim3(QKV_DIM / 128, ROWS / 128), 256, GSM_TOTAL>>>(
        xh, xl, wqh, wql, qkv, QKV_DIM);

    rope_kernel<<<ROWS / 8, 256>>>(qkv);

    int attn_smem = (128 * 32 * 2 + 128 * 129 + 128) * (int)sizeof(float);
    cudaFuncSetAttribute(attn_kernel,
                         cudaFuncAttributeMaxDynamicSharedMemorySize, attn_smem);
    attn_kernel<<<BATCH * SEQ * NUM_HEAD, 128, attn_smem>>>(qkv, pair_mask, ath, atl);

    gemm_bf16x3<<<dim3(MODEL_DIM / 128, ROWS / 128), 256, GSM_TOTAL>>>(
        ath, atl, woh, wol, out, MODEL_DIM);
}

// round 8
// speedup vs baseline: 1.4874x; 1.0145x over previous
#include <cuda_runtime.h>
#include <cuda_bf16.h>
#include <math.h>
#include <cstdint>

// Problem constants (fixed by setup_inputs)
#define BATCH 2
#define SEQ 128
#define MODEL_DIM 256
#define NUM_HEAD 8
#define HEAD_DIM 32
#define ROWS (BATCH * SEQ * SEQ)        // 32768 token rows
#define QKV_DIM (3 * MODEL_DIM)         // 768
#define GK 256                          // GEMM K (= MODEL_DIM)
#define LN_EPS 1e-5f
#define MASK_BIAS -1000000000.0f
#define SCALE 0.17677669529663687f      // 32^-0.5

// Scratch (device globals; no allocations allowed)
__device__ __nv_bfloat16 g_xh[ROWS * MODEL_DIM];
__device__ __nv_bfloat16 g_xl[ROWS * MODEL_DIM];
__device__ float         g_qkv[ROWS * QKV_DIM];
__device__ __nv_bfloat16 g_ath[ROWS * MODEL_DIM];
__device__ __nv_bfloat16 g_atl[ROWS * MODEL_DIM];
__device__ __nv_bfloat16 g_wqh[QKV_DIM * MODEL_DIM];
__device__ __nv_bfloat16 g_wql[QKV_DIM * MODEL_DIM];
__device__ __nv_bfloat16 g_woh[MODEL_DIM * MODEL_DIM];
__device__ __nv_bfloat16 g_wol[MODEL_DIM * MODEL_DIM];
__device__ int g_mask_kind;             // 0=u8 bytes, 1=int32, 2=float32

// ---------------------------------------------------------------------------
__device__ __forceinline__ uint32_t smem_u32(const void* p) {
    uint32_t a;
    asm("{ .reg .u64 t; cvta.to.shared.u64 t, %1; cvt.u32.u64 %0, t; }"
        : "=r"(a) : "l"(p));
    return a;
}

#define CP_ASYNC16(dst, src) \
    asm volatile("cp.async.cg.shared.global [%0], [%1], 16;" \
        :: "r"(dst), "l"(src) : "memory")
#define CP_COMMIT() asm volatile("cp.async.commit_group;" ::: "memory")

#define LDSM4(r, addr) \
    asm volatile("ldmatrix.sync.aligned.m8n8.x4.shared.b16 {%0,%1,%2,%3}, [%4];" \
        : "=r"((r)[0]), "=r"((r)[1]), "=r"((r)[2]), "=r"((r)[3]) : "r"(addr))

#define MMA16816(c, a, b0, b1) \
    asm volatile("mma.sync.aligned.m16n8k16.row.col.f32.bf16.bf16.f32 " \
        "{%0,%1,%2,%3}, {%4,%5,%6,%7}, {%8,%9}, {%0,%1,%2,%3};" \
        : "+f"((c)[0]), "+f"((c)[1]), "+f"((c)[2]), "+f"((c)[3]) \
        : "r"((a)[0]), "r"((a)[1]), "r"((a)[2]), "r"((a)[3]), "r"(b0), "r"(b1))

// Packed fp32x2 (Blackwell base ISA)
__device__ __forceinline__ uint64_t pk2(float x, float y) {
    uint64_t r;
    asm("mov.b64 %0, {%1, %2};" : "=l"(r) : "f"(x), "f"(y));
    return r;
}
__device__ __forceinline__ void upk2(uint64_t v, float& x, float& y) {
    asm("mov.b64 {%0, %1}, %2;" : "=f"(x), "=f"(y) : "l"(v));
}
__device__ __forceinline__ void fma2(uint64_t& d, uint64_t a, uint64_t b) {
    asm("fma.rn.f32x2 %0, %1, %2, %0;" : "+l"(d) : "l"(a), "l"(b));
}
__device__ __forceinline__ uint64_t mul2(uint64_t a, uint64_t b) {
    uint64_t r;
    asm("mul.rn.f32x2 %0, %1, %2;" : "=l"(r) : "l"(a), "l"(b));
    return r;
}
__device__ __forceinline__ void add2(uint64_t& d, uint64_t a) {
    asm("add.rn.f32x2 %0, %1, %0;" : "+l"(d) : "l"(a));
}

// ===========================================================================
// Mask dtype probe (deterministic)
// ===========================================================================
__global__ void detect_mask_kernel(const unsigned char* __restrict__ p) {
    if (threadIdx.x == 0 && blockIdx.x == 0) {
        int nzoff = 0, maxb = 0;
        for (int i = 0; i < 4096; i++) {
            int v = p[i];
            if (v > maxb) maxb = v;
            if ((i & 3) != 0 && v != 0) nzoff = 1;
        }
        g_mask_kind = nzoff ? (maxb > 1 ? 2 : 0) : 1;
    }
}

// ===========================================================================
// LayerNorm fused with bf16 hi/lo split output
// ===========================================================================
__global__ __launch_bounds__(256) void ln_split_kernel(
    const float* __restrict__ x, const float* __restrict__ gamma,
    const float* __restrict__ beta,
    __nv_bfloat16* __restrict__ xh, __nv_bfloat16* __restrict__ xl) {
    int row = blockIdx.x * 8 + threadIdx.y;
    int lane = threadIdx.x;
    const float* xr = x + (size_t)row * MODEL_DIM;
    float v[8];
    float s = 0.f, s2 = 0.f;
#pragma unroll
    for (int i = 0; i < 8; i++) {
        v[i] = xr[lane + i * 32];
        s += v[i];
        s2 += v[i] * v[i];
    }
#pragma unroll
    for (int o = 16; o; o >>= 1) {
        s += __shfl_xor_sync(0xffffffffu, s, o);
        s2 += __shfl_xor_sync(0xffffffffu, s2, o);
    }
    float mean = s * (1.f / 256.f);
    float var = s2 * (1.f / 256.f) - mean * mean;
    float inv = rsqrtf(var + LN_EPS);
    size_t ob = (size_t)row * MODEL_DIM;
#pragma unroll
    for (int i = 0; i < 8; i++) {
        int c = lane + i * 32;
        float y = (v[i] - mean) * inv * gamma[c] + beta[c];
        __nv_bfloat16 h = __float2bfloat16_rn(y);
        xh[ob + c] = h;
        xl[ob + c] = __float2bfloat16_rn(y - __bfloat162float(h));
    }
}

// ===========================================================================
// Combined weight hi/lo split (both Wqkv and Wout in one launch)
// ===========================================================================
#define NQKV (QKV_DIM * MODEL_DIM)
#define NOUT (MODEL_DIM * MODEL_DIM)
__global__ __launch_bounds__(256) void wsplit_all_kernel(
    const float* __restrict__ wq, const float* __restrict__ wo,
    __nv_bfloat16* __restrict__ qh, __nv_bfloat16* __restrict__ ql,
    __nv_bfloat16* __restrict__ oh, __nv_bfloat16* __restrict__ ol) {
    int i = blockIdx.x * 256 + threadIdx.x;
    if (i < NQKV) {
        float v = wq[i];
        __nv_bfloat16 hh = __float2bfloat16_rn(v);
        qh[i] = hh;
        ql[i] = __float2bfloat16_rn(v - __bfloat162float(hh));
    } else if (i < NQKV + NOUT) {
        int j = i - NQKV;
        float v = wo[j];
        __nv_bfloat16 hh = __float2bfloat16_rn(v);
        oh[j] = hh;
        ol[j] = __float2bfloat16_rn(v - __bfloat162float(hh));
    }
}

// ===========================================================================
// bf16 3-term GEMM: C[M,Ntot] = (Ah+Al)[M,256] * (Bh+Bl)[Ntot,256]^T
// ===========================================================================
#define GST 40960
#define GSM_TOTAL (2 * GST)

__global__ __launch_bounds__(256) void gemm_bf16x3(
    const __nv_bfloat16* __restrict__ Ah, const __nv_bfloat16* __restrict__ Al,
    const __nv_bfloat16* __restrict__ Bh, const __nv_bfloat16* __restrict__ Bl,
    float* __restrict__ C, int Ntot) {
    extern __shared__ char smc[];
    uint32_t sb = smem_u32(smc);
    const int t = threadIdx.x;
    const int lane = t & 31;
    const int warp = t >> 5;
    const int wm = warp >> 1;      // 0..3 -> 32 rows
    const int wn = warp & 1;       // 0..1 -> 64 cols
    const int m0 = blockIdx.y * 128;
    const int n0 = blockIdx.x * 128;

    float acc[2][8][4];
#pragma unroll
    for (int i = 0; i < 2; i++)
#pragma unroll
        for (int j = 0; j < 8; j++)
#pragma unroll
            for (int e = 0; e < 4; e++) acc[i][j][e] = 0.f;

    auto issue_stage = [&](int kt, int s) {
        int k0 = kt * 32;
        uint32_t sbase = sb + s * GST;
#pragma unroll
        for (int qq = 0; qq < 2; qq++) {
            int q = t + qq * 256;
            int row = q >> 2;
            int c8 = (q & 3) * 8;
            uint32_t doff = row * 80 + (q & 3) * 16;
            const __nv_bfloat16* ga  = Ah + (size_t)(m0 + row) * GK + k0 + c8;
            const __nv_bfloat16* gal = Al + (size_t)(m0 + row) * GK + k0 + c8;
            const __nv_bfloat16* gb  = Bh + (size_t)(n0 + row) * GK + k0 + c8;
            const __nv_bfloat16* gbl = Bl + (size_t)(n0 + row) * GK + k0 + c8;
            CP_ASYNC16(sbase + doff, ga);
            CP_ASYNC16(sbase + 10240 + doff, gal);
            CP_ASYNC16(sbase + 20480 + doff, gb);
            CP_ASYNC16(sbase + 30720 + doff, gbl);
        }
        CP_COMMIT();
    };

    issue_stage(0, 0);
#pragma unroll 1
    for (int kt = 0; kt < 8; kt++) {
        if (kt < 7) {
            issue_stage(kt + 1, (kt + 1) & 1);
            asm volatile("cp.async.wait_group 1;" ::: "memory");
        } else {
            asm volatile("cp.async.wait_group 0;" ::: "memory");
        }
        __syncthreads();

        uint32_t sbase = sb + (kt & 1) * GST;
        uint32_t sAh = sbase, sAl = sbase + 10240;
        uint32_t sBh = sbase + 20480, sBl = sbase + 30720;
#pragma unroll
        for (int ks = 0; ks < 2; ks++) {
            uint32_t ah[2][4], alr[2][4];
#pragma unroll
            for (int mi = 0; mi < 2; mi++) {
                uint32_t off = ((wm * 32 + mi * 16 + (lane & 15)) * 40 +
                                ks * 16 + (lane >> 4) * 8) * 2;
                LDSM4(ah[mi], sAh + off);
                LDSM4(alr[mi], sAl + off);
            }
            uint32_t bh[4][4], bl[4][4];
#pragma unroll
            for (int ng = 0; ng < 4; ng++) {
                uint32_t off = ((wn * 64 + ng * 16 + (lane & 15)) * 40 +
                                ks * 16 + (lane >> 4) * 8) * 2;
                LDSM4(bh[ng], sBh + off);
                LDSM4(bl[ng], sBl + off);
            }
#pragma unroll
            for (int mi = 0; mi < 2; mi++)
#pragma unroll
                for (int ng = 0; ng < 4; ng++)
#pragma unroll
                    for (int hf = 0; hf < 2; hf++) {
                        int ni = ng * 2 + hf;
                        MMA16816(acc[mi][ni], ah[mi], bh[ng][hf], bh[ng][hf + 2]);
                        MMA16816(acc[mi][ni], alr[mi], bh[ng][hf], bh[ng][hf + 2]);
                        MMA16816(acc[mi][ni], ah[mi], bl[ng][hf], bl[ng][hf + 2]);
                    }
        }
        __syncthreads();
    }

    // epilogue
#pragma unroll
    for (int mi = 0; mi < 2; mi++) {
        int mr = m0 + wm * 32 + mi * 16 + (lane >> 2);
#pragma unroll
        for (int ni = 0; ni < 8; ni++) {
            float* p0 = C + (size_t)mr * Ntot + n0 + wn * 64 + ni * 8 + (lane & 3) * 2;
            *(float2*)p0 = make_float2(acc[mi][ni][0], acc[mi][ni][1]);
            float* p1 = p0 + 8 * (size_t)Ntot;
            *(float2*)p1 = make_float2(acc[mi][ni][2], acc[mi][ni][3]);
        }
    }
}

// ===========================================================================
// Axial rotary: channels [0,32) of q and k sections
// ===========================================================================
__global__ __launch_bounds__(256) void rope_kernel(float* __restrict__ qkv) {
    int row = blockIdx.x * 8 + (threadIdx.x >> 5);
    int t = threadIdx.x & 31;
    int sec = t >> 4;          // 0 = q, 1 = k
    int p = t & 15;
    int x = (row >> 7) & 127;
    int y = row & 127;
    int pos = (p < 8) ? x : y;
    int j = p & 7;
    float tl = -1.f + 2.f * (float)pos * (1.f / 127.f);
    float invf = expf(-1.1512925464970229f * (float)j);
    float theta = tl * invf;
    float c, s;
    sincosf(theta, &s, &c);
    float* base = qkv + (size_t)row * QKV_DIM + sec * MODEL_DIM + 2 * p;
    float a = base[0];
    float b = base[1];
    base[0] = a * c - b * s;
    base[1] = b * c + a * s;
}

// ===========================================================================
// Attention with packed f32x2 math: one CTA per (b*x, head).
// ===========================================================================
__global__ __launch_bounds__(128) void attn_kernel(
    const float* __restrict__ qkv, const void* __restrict__ pmask,
    __nv_bfloat16* __restrict__ oh, __nv_bfloat16* __restrict__ ol) {
    int h = blockIdx.x & 7;
    int bx = blockIdx.x >> 3;
    extern __shared__ float sm[];
    float* Ks = sm;                 // 128*32
    float* Vs = Ks + 128 * 32;      // 128*32
    float* S  = Vs + 128 * 32;      // 128*129
    float* Ms = S + 128 * 129;      // 128 mask flags
    int t = threadIdx.x;
    size_t rowbase = (size_t)bx * 128;
    const float* base = qkv + rowbase * QKV_DIM;

    for (int e = t; e < 128 * 32; e += 128) {
        int y = e >> 5, d = e & 31;
        Ks[e] = base[(size_t)y * QKV_DIM + MODEL_DIM + h * HEAD_DIM + d];
        Vs[e] = base[(size_t)y * QKV_DIM + 2 * MODEL_DIM + h * HEAD_DIM + d];
    }
    for (int e = t; e < 128 * 32; e += 128) {
        int y = e >> 5, d = e & 31;
        S[y * 33 + d] = base[(size_t)y * QKV_DIM + h * HEAD_DIM + d];
    }
    {
        int kind = g_mask_kind;
        size_t midx = (size_t)bx * 128 + t;
        bool mset;
        if (kind == 0)      mset = ((const unsigned char*)pmask)[midx] != 0;
        else if (kind == 1) mset = ((const int*)pmask)[midx] != 0;
        else                mset = ((const float*)pmask)[midx] != 0.f;
        Ms[t] = mset ? 1.f : 0.f;
    }
    __syncthreads();

    uint64_t q2[16];
#pragma unroll
    for (int i = 0; i < 16; i++)
        q2[i] = pk2(S[t * 33 + 2 * i], S[t * 33 + 2 * i + 1]);
    __syncthreads();

    // ---- scores: q . K^T with f32x2 (4 independent chains) ----
    float mx = -1e30f;
    for (int k = 0; k < 128; k++) {
        const ulonglong2* kr = (const ulonglong2*)(Ks + k * 32);
        ulonglong2 kk0 = kr[0];
        ulonglong2 kk1 = kr[1];
        uint64_t c0 = mul2(q2[0], kk0.x);
        uint64_t c1 = mul2(q2[1], kk0.y);
        uint64_t c2 = mul2(q2[2], kk1.x);
        uint64_t c3 = mul2(q2[3], kk1.y);
#pragma unroll
        for (int j = 2; j < 8; j += 2) {
            ulonglong2 ka = kr[j];
            ulonglong2 kb = kr[j + 1];
            fma2(c0, q2[2 * j + 0], ka.x);
            fma2(c1, q2[2 * j + 1], ka.y);
            fma2(c2, q2[2 * j + 2], kb.x);
            fma2(c3, q2[2 * j + 3], kb.y);
        }
        add2(c0, c2);
        add2(c1, c3);
        add2(c0, c1);
        float sx, sy;
        upk2(c0, sx, sy);
        float s = sx + sy;
        s = (Ms[k] != 0.f) ? MASK_BIAS : s * SCALE;
        S[t * 129 + k] = s;
        mx = fmaxf(mx, s);
    }
    float l = 0.f;
    for (int k = 0; k < 128; k++) {
        float p = __expf(S[t * 129 + k] - mx);
        S[t * 129 + k] = p;
        l += p;
    }
    float inv = 1.f / l;

    // ---- PV with f32x2 ----
    uint64_t acc2[16];
    {
        float p0 = S[t * 129 + 0];
        uint64_t pp = pk2(p0, p0);
        const ulonglong2* vr = (const ulonglong2*)(Vs + 0);
#pragma unroll
        for (int j = 0; j < 8; j++) {
            ulonglong2 vv = vr[j];
            acc2[2 * j + 0] = mul2(pp, vv.x);
            acc2[2 * j + 1] = mul2(pp, vv.y);
        }
    }
    for (int k = 1; k < 128; k++) {
        float p = S[t * 129 + k];
        uint64_t pp = pk2(p, p);
        const ulonglong2* vr = (const ulonglong2*)(Vs + k * 32);
#pragma unroll
        for (int j = 0; j < 8; j++) {
            ulonglong2 vv = vr[j];
            fma2(acc2[2 * j + 0], pp, vv.x);
            fma2(acc2[2 * j + 1], pp, vv.y);
        }
    }

    size_t obase = (rowbase + t) * MODEL_DIM + h * HEAD_DIM;
    uint64_t inv2 = pk2(inv, inv);
#pragma unroll
    for (int j = 0; j < 16; j++) {
        float v0, v1;
        upk2(mul2(acc2[j], inv2), v0, v1);
        __nv_bfloat16 h0 = __float2bfloat16_rn(v0);
        __nv_bfloat16 h1 = __float2bfloat16_rn(v1);
        oh[obase + 2 * j + 0] = h0;
        oh[obase + 2 * j + 1] = h1;
        ol[obase + 2 * j + 0] = __float2bfloat16_rn(v0 - __bfloat162float(h0));
        ol[obase + 2 * j + 1] = __float2bfloat16_rn(v1 - __bfloat162float(h1));
    }
}

// ===========================================================================
extern "C" void kernel_launch(void* const* d_in, const int* in_sizes, int n_in,
                              void* d_out, int out_size) {
    const float* pair_act = (const float*)d_in[0];
    const void*  pair_mask = d_in[1];
    const float* ln_gamma = (const float*)d_in[2];
    const float* ln_beta  = (const float*)d_in[3];
    const float* Wqkv = (const float*)d_in[4];
    const float* Wout = (const float*)d_in[5];
    float* out = (float*)d_out;

    __nv_bfloat16 *xh, *xl, *ath, *atl, *wqh, *wql, *woh, *wol;
    float* qkv;
    cudaGetSymbolAddress((void**)&xh, g_xh);
    cudaGetSymbolAddress((void**)&xl, g_xl);
    cudaGetSymbolAddress((void**)&qkv, g_qkv);
    cudaGetSymbolAddress((void**)&ath, g_ath);
    cudaGetSymbolAddress((void**)&atl, g_atl);
    cudaGetSymbolAddress((void**)&wqh, g_wqh);
    cudaGetSymbolAddress((void**)&wql, g_wql);
    cudaGetSymbolAddress((void**)&woh, g_woh);
    cudaGetSymbolAddress((void**)&wol, g_wol);

    // Launch order matters: the harness ncu capture profiles the 4th launch,
    // which is now the QKV GEMM (the dominant kernel).
    detect_mask_kernel<<<1, 32>>>((const unsigned char*)pair_mask);

    ln_split_kernel<<<ROWS / 8, dim3(32, 8)>>>(pair_act, ln_gamma, ln_beta, xh, xl);

    wsplit_all_kernel<<<(NQKV + NOUT + 255) / 256, 256>>>(
        Wqkv, Wout, wqh, wql, woh, wol);

    cudaFuncSetAttribute(gemm_bf16x3,
                         cudaFuncAttributeMaxDynamicSharedMemorySize, GSM_TOTAL);
    gemm_bf16x3<<<dim3(QKV_DIM / 128, ROWS / 128), 256, GSM_TOTAL>>>(
        xh, xl, wqh, wql, qkv, QKV_DIM);

    rope_kernel<<<ROWS / 8, 256>>>(qkv);

    int attn_smem = (128 * 32 * 2 + 128 * 129 + 128) * (int)sizeof(float);
    cudaFuncSetAttribute(attn_kernel,
                         cudaFuncAttributeMaxDynamicSharedMemorySize, attn_smem);
    attn_kernel<<<BATCH * SEQ * NUM_HEAD, 128, attn_smem>>>(qkv, pair_mask, ath, atl);

    gemm_bf16x3<<<dim3(MODEL_DIM / 128, ROWS / 128), 256, GSM_TOTAL>>>(
        ath, atl, woh, wol, out, MODEL_DIM);
}

// round 9
// speedup vs baseline: 1.8963x; 1.2749x over previous
#include <cuda_runtime.h>
#include <cuda_bf16.h>
#include <math.h>
#include <cstdint>

// Problem constants (fixed by setup_inputs)
#define BATCH 2
#define SEQ 128
#define MODEL_DIM 256
#define NUM_HEAD 8
#define HEAD_DIM 32
#define ROWS (BATCH * SEQ * SEQ)        // 32768 token rows
#define QKV_DIM (3 * MODEL_DIM)         // 768
#define GK 256                          // GEMM K (= MODEL_DIM)
#define LN_EPS 1e-5f
#define MASK_BIAS -1000000000.0f
#define SCALE 0.17677669529663687f      // 32^-0.5

// Scratch (device globals; no allocations allowed)
__device__ __nv_bfloat16 g_xh[ROWS * MODEL_DIM];
__device__ __nv_bfloat16 g_xl[ROWS * MODEL_DIM];
__device__ float         g_qkv[ROWS * QKV_DIM];
__device__ __nv_bfloat16 g_ath[ROWS * MODEL_DIM];
__device__ __nv_bfloat16 g_atl[ROWS * MODEL_DIM];
__device__ __nv_bfloat16 g_wqh[QKV_DIM * MODEL_DIM];
__device__ __nv_bfloat16 g_wql[QKV_DIM * MODEL_DIM];
__device__ __nv_bfloat16 g_woh[MODEL_DIM * MODEL_DIM];
__device__ __nv_bfloat16 g_wol[MODEL_DIM * MODEL_DIM];
__device__ int g_mask_kind;             // 0=u8 bytes, 1=int32, 2=float32

// ---------------------------------------------------------------------------
__device__ __forceinline__ uint32_t smem_u32(const void* p) {
    uint32_t a;
    asm("{ .reg .u64 t; cvta.to.shared.u64 t, %1; cvt.u32.u64 %0, t; }"
        : "=r"(a) : "l"(p));
    return a;
}

#define CP_ASYNC16(dst, src) \
    asm volatile("cp.async.cg.shared.global [%0], [%1], 16;" \
        :: "r"(dst), "l"(src) : "memory")
#define CP_COMMIT() asm volatile("cp.async.commit_group;" ::: "memory")

#define LDSM4(r, addr) \
    asm volatile("ldmatrix.sync.aligned.m8n8.x4.shared.b16 {%0,%1,%2,%3}, [%4];" \
        : "=r"((r)[0]), "=r"((r)[1]), "=r"((r)[2]), "=r"((r)[3]) : "r"(addr))

#define MMA16816(c, a, b0, b1) \
    asm volatile("mma.sync.aligned.m16n8k16.row.col.f32.bf16.bf16.f32 " \
        "{%0,%1,%2,%3}, {%4,%5,%6,%7}, {%8,%9}, {%0,%1,%2,%3};" \
        : "+f"((c)[0]), "+f"((c)[1]), "+f"((c)[2]), "+f"((c)[3]) \
        : "r"((a)[0]), "r"((a)[1]), "r"((a)[2]), "r"((a)[3]), "r"(b0), "r"(b1))

__device__ __forceinline__ uint32_t pack_bf16(__nv_bfloat16 a, __nv_bfloat16 b) {
    return (uint32_t)__bfloat16_as_ushort(a) |
           ((uint32_t)__bfloat16_as_ushort(b) << 16);
}

// ===========================================================================
// Mask dtype probe (parallel, deterministic)
// ===========================================================================
__global__ void detect_mask_kernel(const unsigned char* __restrict__ p) {
    __shared__ int s_nz, s_mx;
    int t = threadIdx.x;
    if (t == 0) { s_nz = 0; s_mx = 0; }
    __syncthreads();
    int nz = 0, mx = 0;
    for (int i = t; i < 4096; i += 128) {
        int v = p[i];
        if (v > mx) mx = v;
        if ((i & 3) != 0 && v != 0) nz = 1;
    }
    atomicMax(&s_mx, mx);
    atomicOr(&s_nz, nz);
    __syncthreads();
    if (t == 0) g_mask_kind = s_nz ? (s_mx > 1 ? 2 : 0) : 1;
}

// ===========================================================================
// LayerNorm fused with bf16 hi/lo split output
// ===========================================================================
__global__ __launch_bounds__(256) void ln_split_kernel(
    const float* __restrict__ x, const float* __restrict__ gamma,
    const float* __restrict__ beta,
    __nv_bfloat16* __restrict__ xh, __nv_bfloat16* __restrict__ xl) {
    int row = blockIdx.x * 8 + threadIdx.y;
    int lane = threadIdx.x;
    const float* xr = x + (size_t)row * MODEL_DIM;
    float v[8];
    float s = 0.f, s2 = 0.f;
#pragma unroll
    for (int i = 0; i < 8; i++) {
        v[i] = xr[lane + i * 32];
        s += v[i];
        s2 += v[i] * v[i];
    }
#pragma unroll
    for (int o = 16; o; o >>= 1) {
        s += __shfl_xor_sync(0xffffffffu, s, o);
        s2 += __shfl_xor_sync(0xffffffffu, s2, o);
    }
    float mean = s * (1.f / 256.f);
    float var = s2 * (1.f / 256.f) - mean * mean;
    float inv = rsqrtf(var + LN_EPS);
    size_t ob = (size_t)row * MODEL_DIM;
#pragma unroll
    for (int i = 0; i < 8; i++) {
        int c = lane + i * 32;
        float y = (v[i] - mean) * inv * gamma[c] + beta[c];
        __nv_bfloat16 h = __float2bfloat16_rn(y);
        xh[ob + c] = h;
        xl[ob + c] = __float2bfloat16_rn(y - __bfloat162float(h));
    }
}

// ===========================================================================
// Combined weight hi/lo split
// ===========================================================================
#define NQKV (QKV_DIM * MODEL_DIM)
#define NOUT (MODEL_DIM * MODEL_DIM)
__global__ __launch_bounds__(256) void wsplit_all_kernel(
    const float* __restrict__ wq, const float* __restrict__ wo,
    __nv_bfloat16* __restrict__ qh, __nv_bfloat16* __restrict__ ql,
    __nv_bfloat16* __restrict__ oh, __nv_bfloat16* __restrict__ ol) {
    int i = blockIdx.x * 256 + threadIdx.x;
    if (i < NQKV) {
        float v = wq[i];
        __nv_bfloat16 hh = __float2bfloat16_rn(v);
        qh[i] = hh;
        ql[i] = __float2bfloat16_rn(v - __bfloat162float(hh));
    } else if (i < NQKV + NOUT) {
        int j = i - NQKV;
        float v = wo[j];
        __nv_bfloat16 hh = __float2bfloat16_rn(v);
        oh[j] = hh;
        ol[j] = __float2bfloat16_rn(v - __bfloat162float(hh));
    }
}

// ===========================================================================
// bf16 3-term GEMM (unchanged from R8)
// ===========================================================================
#define GST 40960
#define GSM_TOTAL (2 * GST)

__global__ __launch_bounds__(256) void gemm_bf16x3(
    const __nv_bfloat16* __restrict__ Ah, const __nv_bfloat16* __restrict__ Al,
    const __nv_bfloat16* __restrict__ Bh, const __nv_bfloat16* __restrict__ Bl,
    float* __restrict__ C, int Ntot) {
    extern __shared__ char smc[];
    uint32_t sb = smem_u32(smc);
    const int t = threadIdx.x;
    const int lane = t & 31;
    const int warp = t >> 5;
    const int wm = warp >> 1;
    const int wn = warp & 1;
    const int m0 = blockIdx.y * 128;
    const int n0 = blockIdx.x * 128;

    float acc[2][8][4];
#pragma unroll
    for (int i = 0; i < 2; i++)
#pragma unroll
        for (int j = 0; j < 8; j++)
#pragma unroll
            for (int e = 0; e < 4; e++) acc[i][j][e] = 0.f;

    auto issue_stage = [&](int kt, int s) {
        int k0 = kt * 32;
        uint32_t sbase = sb + s * GST;
#pragma unroll
        for (int qq = 0; qq < 2; qq++) {
            int q = t + qq * 256;
            int row = q >> 2;
            int c8 = (q & 3) * 8;
            uint32_t doff = row * 80 + (q & 3) * 16;
            const __nv_bfloat16* ga  = Ah + (size_t)(m0 + row) * GK + k0 + c8;
            const __nv_bfloat16* gal = Al + (size_t)(m0 + row) * GK + k0 + c8;
            const __nv_bfloat16* gb  = Bh + (size_t)(n0 + row) * GK + k0 + c8;
            const __nv_bfloat16* gbl = Bl + (size_t)(n0 + row) * GK + k0 + c8;
            CP_ASYNC16(sbase + doff, ga);
            CP_ASYNC16(sbase + 10240 + doff, gal);
            CP_ASYNC16(sbase + 20480 + doff, gb);
            CP_ASYNC16(sbase + 30720 + doff, gbl);
        }
        CP_COMMIT();
    };

    issue_stage(0, 0);
#pragma unroll 1
    for (int kt = 0; kt < 8; kt++) {
        if (kt < 7) {
            issue_stage(kt + 1, (kt + 1) & 1);
            asm volatile("cp.async.wait_group 1;" ::: "memory");
        } else {
            asm volatile("cp.async.wait_group 0;" ::: "memory");
        }
        __syncthreads();

        uint32_t sbase = sb + (kt & 1) * GST;
        uint32_t sAh = sbase, sAl = sbase + 10240;
        uint32_t sBh = sbase + 20480, sBl = sbase + 30720;
#pragma unroll
        for (int ks = 0; ks < 2; ks++) {
            uint32_t ah[2][4], alr[2][4];
#pragma unroll
            for (int mi = 0; mi < 2; mi++) {
                uint32_t off = ((wm * 32 + mi * 16 + (lane & 15)) * 40 +
                                ks * 16 + (lane >> 4) * 8) * 2;
                LDSM4(ah[mi], sAh + off);
                LDSM4(alr[mi], sAl + off);
            }
            uint32_t bh[4][4], bl[4][4];
#pragma unroll
            for (int ng = 0; ng < 4; ng++) {
                uint32_t off = ((wn * 64 + ng * 16 + (lane & 15)) * 40 +
                                ks * 16 + (lane >> 4) * 8) * 2;
                LDSM4(bh[ng], sBh + off);
                LDSM4(bl[ng], sBl + off);
            }
#pragma unroll
            for (int mi = 0; mi < 2; mi++)
#pragma unroll
                for (int ng = 0; ng < 4; ng++)
#pragma unroll
                    for (int hf = 0; hf < 2; hf++) {
                        int ni = ng * 2 + hf;
                        MMA16816(acc[mi][ni], ah[mi], bh[ng][hf], bh[ng][hf + 2]);
                        MMA16816(acc[mi][ni], alr[mi], bh[ng][hf], bh[ng][hf + 2]);
                        MMA16816(acc[mi][ni], ah[mi], bl[ng][hf], bl[ng][hf + 2]);
                    }
        }
        __syncthreads();
    }

#pragma unroll
    for (int mi = 0; mi < 2; mi++) {
        int mr = m0 + wm * 32 + mi * 16 + (lane >> 2);
#pragma unroll
        for (int ni = 0; ni < 8; ni++) {
            float* p0 = C + (size_t)mr * Ntot + n0 + wn * 64 + ni * 8 + (lane & 3) * 2;
            *(float2*)p0 = make_float2(acc[mi][ni][0], acc[mi][ni][1]);
            float* p1 = p0 + 8 * (size_t)Ntot;
            *(float2*)p1 = make_float2(acc[mi][ni][2], acc[mi][ni][3]);
        }
    }
}

// ===========================================================================
// Axial rotary: channels [0,32) of q and k sections
// ===========================================================================
__global__ __launch_bounds__(256) void rope_kernel(float* __restrict__ qkv) {
    int row = blockIdx.x * 8 + (threadIdx.x >> 5);
    int t = threadIdx.x & 31;
    int sec = t >> 4;
    int p = t & 15;
    int x = (row >> 7) & 127;
    int y = row & 127;
    int pos = (p < 8) ? x : y;
    int j = p & 7;
    float tl = -1.f + 2.f * (float)pos * (1.f / 127.f);
    float invf = expf(-1.1512925464970229f * (float)j);
    float theta = tl * invf;
    float c, s;
    sincosf(theta, &s, &c);
    float* base = qkv + (size_t)row * QKV_DIM + sec * MODEL_DIM + 2 * p;
    float a = base[0];
    float b = base[1];
    base[0] = a * c - b * s;
    base[1] = b * c + a * s;
}

// ===========================================================================
// Tensor-core attention: one CTA per (bx, head), 256 threads (8 warps).
// S = Q K^T (3-term bf16 mma) -> softmax (128 threads) -> O = P V (3-term).
// smem byte offsets:
//   KH 0       KL 10240   QH 20480   QL 30720   (128 rows x 40 bf16)
//   VTH 40960  VTL 49664                        (32 rows x 136 bf16)
//   S  58368   (128 x 132 fp32)
//   PH 125952  PL 160768  (128 x 136 bf16)
//   MS 195584  (128 fp32)   LI 196096 (128 fp32)  total 196608
// ===========================================================================
#define A_KH 0
#define A_KL 10240
#define A_QH 20480
#define A_QL 30720
#define A_VTH 40960
#define A_VTL 49664
#define A_S 58368
#define A_PH 125952
#define A_PL 160768
#define A_MS 195584
#define A_LI 196096
#define ATTN_SMEM 196608

__global__ __launch_bounds__(256) void attn_tc_kernel(
    const float* __restrict__ qkv, const void* __restrict__ pmask,
    __nv_bfloat16* __restrict__ oh, __nv_bfloat16* __restrict__ ol) {
    extern __shared__ char sm[];
    uint32_t sb = smem_u32(sm);
    int t = threadIdx.x;
    int lane = t & 31;
    int w = t >> 5;
    int h = blockIdx.x & 7;
    int bx = blockIdx.x >> 3;
    size_t rowbase = (size_t)bx * 128;
    const float* base = qkv + rowbase * QKV_DIM;

    // ---- load + hi/lo split (V transposed) ----
    for (int e = t; e < 4096; e += 256) {
        int y = e >> 5, d = e & 31;
        size_t rb = (size_t)y * QKV_DIM + h * 32 + d;
        float qv = base[rb];
        float kv = base[rb + 256];
        float vv = base[rb + 512];
        __nv_bfloat16 hh;
        uint32_t o = (y * 40 + d) * 2;
        hh = __float2bfloat16_rn(qv);
        *(__nv_bfloat16*)(sm + A_QH + o) = hh;
        *(__nv_bfloat16*)(sm + A_QL + o) = __float2bfloat16_rn(qv - __bfloat162float(hh));
        hh = __float2bfloat16_rn(kv);
        *(__nv_bfloat16*)(sm + A_KH + o) = hh;
        *(__nv_bfloat16*)(sm + A_KL + o) = __float2bfloat16_rn(kv - __bfloat162float(hh));
        uint32_t ov = (d * 136 + y) * 2;
        hh = __float2bfloat16_rn(vv);
        *(__nv_bfloat16*)(sm + A_VTH + ov) = hh;
        *(__nv_bfloat16*)(sm + A_VTL + ov) = __float2bfloat16_rn(vv - __bfloat162float(hh));
    }
    if (t < 128) {
        int kind = g_mask_kind;
        size_t midx = rowbase + t;
        bool mset;
        if (kind == 0)      mset = ((const unsigned char*)pmask)[midx] != 0;
        else if (kind == 1) mset = ((const int*)pmask)[midx] != 0;
        else                mset = ((const float*)pmask)[midx] != 0.f;
        ((float*)(sm + A_MS))[t] = mset ? 1.f : 0.f;
    }
    __syncthreads();

    // ---- S = Q K^T (each warp: 16 q-rows x all 128 k) ----
    {
        float acc[16][4];
#pragma unroll
        for (int i = 0; i < 16; i++)
#pragma unroll
            for (int e = 0; e < 4; e++) acc[i][e] = 0.f;
        int m0 = w * 16;
#pragma unroll
        for (int ks = 0; ks < 2; ks++) {
            uint32_t aoff = ((m0 + (lane & 15)) * 40 + ks * 16 + (lane >> 4) * 8) * 2;
            uint32_t ah[4], al[4];
            LDSM4(ah, sb + A_QH + aoff);
            LDSM4(al, sb + A_QL + aoff);
#pragma unroll
            for (int ng = 0; ng < 8; ng++) {
                uint32_t boff = ((ng * 16 + (lane & 15)) * 40 + ks * 16 + (lane >> 4) * 8) * 2;
                uint32_t bh[4], bl[4];
                LDSM4(bh, sb + A_KH + boff);
                LDSM4(bl, sb + A_KL + boff);
#pragma unroll
                for (int hf = 0; hf < 2; hf++) {
                    int ni = ng * 2 + hf;
                    MMA16816(acc[ni], ah, bh[hf], bh[hf + 2]);
                    MMA16816(acc[ni], al, bh[hf], bh[hf + 2]);
                    MMA16816(acc[ni], ah, bl[hf], bl[hf + 2]);
                }
            }
        }
        float* Sp = (float*)(sm + A_S);
        int r0 = m0 + (lane >> 2);
#pragma unroll
        for (int ni = 0; ni < 16; ni++) {
            int c = ni * 8 + (lane & 3) * 2;
            *(float2*)&Sp[r0 * 132 + c] = make_float2(acc[ni][0], acc[ni][1]);
            *(float2*)&Sp[(r0 + 8) * 132 + c] = make_float2(acc[ni][2], acc[ni][3]);
        }
    }
    __syncthreads();

    // ---- softmax: thread t owns q-row t; emit P as bf16 hi/lo ----
    if (t < 128) {
        float4* Sp4 = (float4*)((float*)(sm + A_S) + t * 132);
        const float4* M4 = (const float4*)(sm + A_MS);
        float mx = -1e30f;
#pragma unroll 8
        for (int i = 0; i < 32; i++) {
            float4 sv = Sp4[i];
            float4 mv = M4[i];
            sv.x = (mv.x != 0.f) ? MASK_BIAS : sv.x * SCALE;
            sv.y = (mv.y != 0.f) ? MASK_BIAS : sv.y * SCALE;
            sv.z = (mv.z != 0.f) ? MASK_BIAS : sv.z * SCALE;
            sv.w = (mv.w != 0.f) ? MASK_BIAS : sv.w * SCALE;
            Sp4[i] = sv;
            mx = fmaxf(mx, fmaxf(fmaxf(sv.x, sv.y), fmaxf(sv.z, sv.w)));
        }
        float l = 0.f;
        uint2* P2h = (uint2*)(sm + A_PH + t * 272);
        uint2* P2l = (uint2*)(sm + A_PL + t * 272);
#pragma unroll 8
        for (int i = 0; i < 32; i++) {
            float4 sv = Sp4[i];
            float p0 = __expf(sv.x - mx);
            float p1 = __expf(sv.y - mx);
            float p2 = __expf(sv.z - mx);
            float p3 = __expf(sv.w - mx);
            l += (p0 + p1) + (p2 + p3);
            __nv_bfloat16 h0 = __float2bfloat16_rn(p0);
            __nv_bfloat16 h1 = __float2bfloat16_rn(p1);
            __nv_bfloat16 h2 = __float2bfloat16_rn(p2);
            __nv_bfloat16 h3 = __float2bfloat16_rn(p3);
            P2h[i] = make_uint2(pack_bf16(h0, h1), pack_bf16(h2, h3));
            P2l[i] = make_uint2(
                pack_bf16(__float2bfloat16_rn(p0 - __bfloat162float(h0)),
                          __float2bfloat16_rn(p1 - __bfloat162float(h1))),
                pack_bf16(__float2bfloat16_rn(p2 - __bfloat162float(h2)),
                          __float2bfloat16_rn(p3 - __bfloat162float(h3))));
        }
        ((float*)(sm + A_LI))[t] = 1.f / l;
    }
    __syncthreads();

    // ---- O = P V (each warp: 16 q-rows x 32 d) ----
    {
        float acc[4][4];
#pragma unroll
        for (int i = 0; i < 4; i++)
#pragma unroll
            for (int e = 0; e < 4; e++) acc[i][e] = 0.f;
        int m0 = w * 16;
#pragma unroll
        for (int ks = 0; ks < 8; ks++) {
            uint32_t aoff = ((m0 + (lane & 15)) * 136 + ks * 16 + (lane >> 4) * 8) * 2;
            uint32_t ph[4], pl[4];
            LDSM4(ph, sb + A_PH + aoff);
            LDSM4(pl, sb + A_PL + aoff);
#pragma unroll
            for (int dg = 0; dg < 2; dg++) {
                uint32_t boff = ((dg * 16 + (lane & 15)) * 136 + ks * 16 + (lane >> 4) * 8) * 2;
                uint32_t vh[4], vl[4];
                LDSM4(vh, sb + A_VTH + boff);
                LDSM4(vl, sb + A_VTL + boff);
#pragma unroll
                for (int hf = 0; hf < 2; hf++) {
                    int ni = dg * 2 + hf;
                    MMA16816(acc[ni], ph, vh[hf], vh[hf + 2]);
                    MMA16816(acc[ni], pl, vh[hf], vh[hf + 2]);
                    MMA16816(acc[ni], ph, vl[hf], vl[hf + 2]);
                }
            }
        }
        const float* LI = (const float*)(sm + A_LI);
        int r0 = m0 + (lane >> 2);
        float i0 = LI[r0];
        float i1 = LI[r0 + 8];
#pragma unroll
        for (int ni = 0; ni < 4; ni++) {
            int c = ni * 8 + (lane & 3) * 2;
#pragma unroll
            for (int half = 0; half < 2; half++) {
                int r = half ? (r0 + 8) : r0;
                float v0 = acc[ni][2 * half + 0] * (half ? i1 : i0);
                float v1 = acc[ni][2 * half + 1] * (half ? i1 : i0);
                size_t gi = (rowbase + r) * MODEL_DIM + h * 32 + c;
                __nv_bfloat16 h0 = __float2bfloat16_rn(v0);
                __nv_bfloat16 h1 = __float2bfloat16_rn(v1);
                __nv_bfloat162 ph2; ph2.x = h0; ph2.y = h1;
                *(__nv_bfloat162*)(oh + gi) = ph2;
                __nv_bfloat162 pl2;
                pl2.x = __float2bfloat16_rn(v0 - __bfloat162float(h0));
                pl2.y = __float2bfloat16_rn(v1 - __bfloat162float(h1));
                *(__nv_bfloat162*)(ol + gi) = pl2;
            }
        }
    }
}

// ===========================================================================
extern "C" void kernel_launch(void* const* d_in, const int* in_sizes, int n_in,
                              void* d_out, int out_size) {
    const float* pair_act = (const float*)d_in[0];
    const void*  pair_mask = d_in[1];
    const float* ln_gamma = (const float*)d_in[2];
    const float* ln_beta  = (const float*)d_in[3];
    const float* Wqkv = (const float*)d_in[4];
    const float* Wout = (const float*)d_in[5];
    float* out = (float*)d_out;

    __nv_bfloat16 *xh, *xl, *ath, *atl, *wqh, *wql, *woh, *wol;
    float* qkv;
    cudaGetSymbolAddress((void**)&xh, g_xh);
    cudaGetSymbolAddress((void**)&xl, g_xl);
    cudaGetSymbolAddress((void**)&qkv, g_qkv);
    cudaGetSymbolAddress((void**)&ath, g_ath);
    cudaGetSymbolAddress((void**)&atl, g_atl);
    cudaGetSymbolAddress((void**)&wqh, g_wqh);
    cudaGetSymbolAddress((void**)&wql, g_wql);
    cudaGetSymbolAddress((void**)&woh, g_woh);
    cudaGetSymbolAddress((void**)&wol, g_wol);

    detect_mask_kernel<<<1, 128>>>((const unsigned char*)pair_mask);

    ln_split_kernel<<<ROWS / 8, dim3(32, 8)>>>(pair_act, ln_gamma, ln_beta, xh, xl);

    wsplit_all_kernel<<<(NQKV + NOUT + 255) / 256, 256>>>(
        Wqkv, Wout, wqh, wql, woh, wol);

    // 4th launch = QKV GEMM (ncu profiles this one)
    cudaFuncSetAttribute(gemm_bf16x3,
                         cudaFuncAttributeMaxDynamicSharedMemorySize, GSM_TOTAL);
    gemm_bf16x3<<<dim3(QKV_DIM / 128, ROWS / 128), 256, GSM_TOTAL>>>(
        xh, xl, wqh, wql, qkv, QKV_DIM);

    rope_kernel<<<ROWS / 8, 256>>>(qkv);

    cudaFuncSetAttribute(attn_tc_kernel,
                         cudaFuncAttributeMaxDynamicSharedMemorySize, ATTN_SMEM);
    attn_tc_kernel<<<BATCH * SEQ * NUM_HEAD, 256, ATTN_SMEM>>>(
        qkv, pair_mask, ath, atl);

    gemm_bf16x3<<<dim3(MODEL_DIM / 128, ROWS / 128), 256, GSM_TOTAL>>>(
        ath, atl, woh, wol, out, MODEL_DIM);
}